// round 17
// baseline (speedup 1.0000x reference)
#include <cuda_runtime.h>
#include <cuda_bf16.h>

#define NB      4
#define RB      72
#define RBP     80          // padded rows for m16 tiles
#define THREADS 512
#define TSTEPS  128
#define NNODE   18
#define DIMX    32
#define HIDN    64
#define STB     136         // bf16 feat row stride (elements)
#define STH     68          // fp32 h/OUT row stride
#define NBLK    128
#define STS2    24

typedef unsigned long long u64;
typedef unsigned int uint;
typedef unsigned short ushort;

// ---------------- packed weights: bf16 hi/lo, transposed [n][k] ----------
__device__ ushort g_wg0h[128 * 480], g_wg0l[128 * 480];
__device__ ushort g_wc0h[64 * 480],  g_wc0l[64 * 480];
__device__ ushort g_wg1h[128 * 640], g_wg1l[128 * 640];
__device__ ushort g_wc1h[64 * 640],  g_wc1l[64 * 640];

// ---------------- helpers ----------------
__device__ __forceinline__ u64 pk2(float a, float b) {
    u64 r;
    asm("mov.b64 %0, {%1, %2};" : "=l"(r)
        : "r"(__float_as_uint(a)), "r"(__float_as_uint(b)));
    return r;
}
__device__ __forceinline__ float2 up2(u64 v) {
    unsigned lo, hi;
    asm("mov.b64 {%0, %1}, %2;" : "=r"(lo), "=r"(hi) : "l"(v));
    return make_float2(__uint_as_float(lo), __uint_as_float(hi));
}
__device__ __forceinline__ void fma2(u64 &d, u64 a, u64 b) {
    asm("fma.rn.f32x2 %0, %1, %2, %0;" : "+l"(d) : "l"(a), "l"(b));
}
__device__ __forceinline__ float ex2f(float x) {
    float r; asm("ex2.approx.ftz.f32 %0, %1;" : "=f"(r) : "f"(x)); return r;
}
__device__ __forceinline__ float rcpf(float x) {
    float r; asm("rcp.approx.ftz.f32 %0, %1;" : "=f"(r) : "f"(x)); return r;
}
__device__ __forceinline__ float sigm(float v) {
    return rcpf(1.f + ex2f(-1.4426950408889634f * v));
}
__device__ __forceinline__ float tanh_(float v) {
    return 1.f - 2.f * rcpf(1.f + ex2f(2.8853900817779268f * v));
}
__device__ __forceinline__ uint bfpack(float x, float y) {
    uint r;
    asm("cvt.rn.bf16x2.f32 %0, %1, %2;" : "=r"(r) : "f"(y), "f"(x));
    return r;
}
__device__ __forceinline__ float bflo(uint u) { return __uint_as_float(u << 16); }
__device__ __forceinline__ float bfhi(uint u) { return __uint_as_float(u & 0xffff0000u); }
__device__ __forceinline__ void split2(float x, float y, uint &h, uint &l) {
    h = bfpack(x, y);
    l = bfpack(x - bflo(h), y - bfhi(h));
}
__device__ __forceinline__ uint s2u(const void* p) {
    uint a;
    asm("{ .reg .u64 t; cvta.to.shared.u64 t, %1; cvt.u32.u64 %0, t; }"
        : "=r"(a) : "l"(p));
    return a;
}

__device__ __forceinline__ void mma16816(float* d, const uint* a, uint b0, uint b1) {
    asm volatile(
        "mma.sync.aligned.m16n8k16.row.col.f32.bf16.bf16.f32 "
        "{%0,%1,%2,%3},{%4,%5,%6,%7},{%8,%9},{%0,%1,%2,%3};"
        : "+f"(d[0]), "+f"(d[1]), "+f"(d[2]), "+f"(d[3])
        : "r"(a[0]), "r"(a[1]), "r"(a[2]), "r"(a[3]), "r"(b0), "r"(b1));
}
__device__ __forceinline__ void ldsm4(uint* r, uint saddr) {
    asm volatile("ldmatrix.sync.aligned.m8n8.x4.shared.b16 {%0,%1,%2,%3}, [%4];"
        : "=r"(r[0]), "=r"(r[1]), "=r"(r[2]), "=r"(r[3]) : "r"(saddr));
}

// ---------------- weight pack kernel ----------------
__global__ void pack_kernel(const float* __restrict__ wg0, const float* __restrict__ wc0,
                            const float* __restrict__ wg1, const float* __restrict__ wc1)
{
    int i = blockIdx.x * 256 + threadIdx.x;
    float v; ushort *ph, *pl; int off;
    if (i < 61440)       { int n = i / 480, k = i % 480; v = wg0[k * 128 + n];
                           ph = g_wg0h; pl = g_wg0l; off = i; }
    else if (i < 92160)  { int j = i - 61440; int n = j / 480, k = j % 480;
                           v = wc0[k * 64 + n]; ph = g_wc0h; pl = g_wc0l; off = j; }
    else if (i < 174080) { int j = i - 92160; int n = j / 640, k = j % 640;
                           v = wg1[k * 128 + n]; ph = g_wg1h; pl = g_wg1l; off = j; }
    else if (i < 215040) { int j = i - 174080; int n = j / 640, k = j % 640;
                           v = wc1[k * 64 + n]; ph = g_wc1h; pl = g_wc1l; off = j; }
    else return;
    __nv_bfloat16 h = __float2bfloat16(v);
    float lo = v - __bfloat162float(h);
    __nv_bfloat16 l = __float2bfloat16(lo);
    ph[off] = __bfloat16_as_ushort(h);
    pl[off] = __bfloat16_as_ushort(l);
}

// ---------------- shared memory ----------------
struct __align__(16) Smem {
    float2 St2[2][NNODE * STS2];
    float hA[RB * STH];
    float hB[RB * STH];
    float U[RB * STH];
    ushort Zh[RBP * STB], Zl[RBP * STB];
    ushort Dah[RBP * STB], Dal[RBP * STB];
    ushort Dbh[RBP * STB], Dbl[RBP * STB];
};

// ---------------- spmm (2 cols/thread, 512-thread map) ----------------
__device__ __forceinline__ void spmm2(const float2* __restrict__ St,
                                      const ushort* __restrict__ srch,
                                      const ushort* __restrict__ srcl,
                                      ushort* __restrict__ dsth,
                                      ushort* __restrict__ dstl,
                                      const ushort* __restrict__ zsubh,
                                      const ushort* __restrict__ zsubl,
                                      int CC, int rbase, int bloc, int nlo, int c0)
{
    if (c0 >= CC) return;
    const int sb = bloc * NNODE * STB + c0;
    u64 a[9];
#pragma unroll
    for (int i = 0; i < 9; i++) a[i] = 0;
    uint Hc = *(const uint*)(srch + sb);
    uint Lc = *(const uint*)(srcl + sb);
#pragma unroll 1
    for (int mm = 0; mm < NNODE; mm++) {
        uint hc = Hc, lc = Lc;
        if (mm + 1 < NNODE) {
            Hc = *(const uint*)(srch + sb + (mm + 1) * STB);
            Lc = *(const uint*)(srcl + sb + (mm + 1) * STB);
        }
        float f0 = bflo(hc) + bflo(lc), f1 = bfhi(hc) + bfhi(lc);
        u64 z1 = pk2(f0, f1);
        const float2* sp = St + mm * STS2 + nlo;
        ulonglong2 p01 = *(const ulonglong2*)(sp);
        ulonglong2 p23 = *(const ulonglong2*)(sp + 2);
        ulonglong2 p45 = *(const ulonglong2*)(sp + 4);
        ulonglong2 p67 = *(const ulonglong2*)(sp + 6);
        u64        p8  = *(const u64*)(sp + 8);
        fma2(a[0], p01.x, z1); fma2(a[1], p01.y, z1);
        fma2(a[2], p23.x, z1); fma2(a[3], p23.y, z1);
        fma2(a[4], p45.x, z1); fma2(a[5], p45.y, z1);
        fma2(a[6], p67.x, z1); fma2(a[7], p67.y, z1);
        fma2(a[8], p8,    z1);
    }
#pragma unroll
    for (int i = 0; i < 9; i++) {
        float2 q = up2(a[i]);
        float v0 = q.x, v1 = q.y;
        int idx = (rbase + i) * STB + c0;
        if (zsubh) {
            uint zh = *(const uint*)(zsubh + idx);
            uint zl = *(const uint*)(zsubl + idx);
            v0 = 2.f * v0 - (bflo(zh) + bflo(zl));
            v1 = 2.f * v1 - (bfhi(zh) + bfhi(zl));
        }
        uint h0, l0;
        split2(v0, v1, h0, l0);
        *(uint*)(dsth + idx) = h0;
        *(uint*)(dstl + idx) = l0;
    }
}

// ---------------- gate GEMM: warp owns 2 n8-tiles x MTN m16-tiles ----------
template<int CC, int MTN>
__device__ __forceinline__ void gemm_gate_mma(uint fhU, uint flU,
                                              const ushort* __restrict__ wth,
                                              const ushort* __restrict__ wtl,
                                              int Kt, int kgbase, int nb,
                                              int lr, int lc, float* dg)
{
    constexpr int KS = CC / 16;
    const ushort* bph = wth + (size_t)(nb + lr) * Kt + kgbase + 2 * lc;
    const ushort* bpl = wtl + (size_t)(nb + lr) * Kt + kgbase + 2 * lc;
    uint bh[2][2], bl[2][2];
#pragma unroll
    for (int j = 0; j < 2; j++) {
        const ushort* p = bph + j * 8 * Kt;
        const ushort* q = bpl + j * 8 * Kt;
        bh[j][0] = __ldg((const uint*)p); bh[j][1] = __ldg((const uint*)(p + 8));
        bl[j][0] = __ldg((const uint*)q); bl[j][1] = __ldg((const uint*)(q + 8));
    }
#pragma unroll 1
    for (int ks = 0; ks < KS; ks++) {
        uint ah[MTN][4], al[MTN][4];
#pragma unroll
        for (int mt = 0; mt < MTN; mt++) {
            uint off = (uint)((mt * 16 * STB + ks * 16) * 2);
            ldsm4(ah[mt], fhU + off);
            ldsm4(al[mt], flU + off);
        }
        uint nh[2][2], nl[2][2];
        if (ks + 1 < KS) {
#pragma unroll
            for (int j = 0; j < 2; j++) {
                const ushort* p = bph + j * 8 * Kt + (ks + 1) * 16;
                const ushort* q = bpl + j * 8 * Kt + (ks + 1) * 16;
                nh[j][0] = __ldg((const uint*)p); nh[j][1] = __ldg((const uint*)(p + 8));
                nl[j][0] = __ldg((const uint*)q); nl[j][1] = __ldg((const uint*)(q + 8));
            }
        }
#pragma unroll
        for (int j = 0; j < 2; j++)
#pragma unroll
            for (int mt = 0; mt < MTN; mt++) {
                float* d = dg + (j * MTN + mt) * 4;
                mma16816(d, ah[mt], bh[j][0], bh[j][1]);
                mma16816(d, al[mt], bh[j][0], bh[j][1]);
                mma16816(d, ah[mt], bl[j][0], bl[j][1]);
            }
        if (ks + 1 < KS) {
#pragma unroll
            for (int j = 0; j < 2; j++) {
                bh[j][0] = nh[j][0]; bh[j][1] = nh[j][1];
                bl[j][0] = nl[j][0]; bl[j][1] = nl[j][1];
            }
        }
    }
}

// ---------------- cand GEMM: warp owns 1 n8-tile x MTN m16-tiles ------------
template<int CC, int MTN>
__device__ __forceinline__ void gemm_cand_mma(uint fhU, uint flU,
                                              const ushort* __restrict__ wth,
                                              const ushort* __restrict__ wtl,
                                              int Kt, int kgbase, int nb,
                                              int lr, int lc, float* dc)
{
    constexpr int KS = CC / 16;
    const ushort* bph = wth + (size_t)(nb + lr) * Kt + kgbase + 2 * lc;
    const ushort* bpl = wtl + (size_t)(nb + lr) * Kt + kgbase + 2 * lc;
    uint b0h = __ldg((const uint*)bph), b1h = __ldg((const uint*)(bph + 8));
    uint b0l = __ldg((const uint*)bpl), b1l = __ldg((const uint*)(bpl + 8));
#pragma unroll 1
    for (int ks = 0; ks < KS; ks++) {
        uint ah[MTN][4], al[MTN][4];
#pragma unroll
        for (int mt = 0; mt < MTN; mt++) {
            uint off = (uint)((mt * 16 * STB + ks * 16) * 2);
            ldsm4(ah[mt], fhU + off);
            ldsm4(al[mt], flU + off);
        }
        uint n0h = 0, n1h = 0, n0l = 0, n1l = 0;
        if (ks + 1 < KS) {
            n0h = __ldg((const uint*)(bph + (ks + 1) * 16));
            n1h = __ldg((const uint*)(bph + (ks + 1) * 16 + 8));
            n0l = __ldg((const uint*)(bpl + (ks + 1) * 16));
            n1l = __ldg((const uint*)(bpl + (ks + 1) * 16 + 8));
        }
#pragma unroll
        for (int mt = 0; mt < MTN; mt++) {
            float* d = dc + mt * 4;
            mma16816(d, ah[mt], b0h, b1h);
            mma16816(d, al[mt], b0h, b1h);
            mma16816(d, ah[mt], b0l, b1l);
        }
        if (ks + 1 < KS) { b0h = n0h; b1h = n1h; b0l = n0l; b1l = n1l; }
    }
}

// ---------------- main persistent kernel ----------------
__global__ void __launch_bounds__(THREADS, 1)
dcrnn_kernel(const float* __restrict__ x,   const float* __restrict__ sup,
             const float* __restrict__ bg0, const float* __restrict__ bc0,
             const float* __restrict__ bg1, const float* __restrict__ bc1,
             const float* __restrict__ fcw, const float* __restrict__ fcb,
             float* __restrict__ out)
{
    extern __shared__ char smraw[];
    Smem& sm = *reinterpret_cast<Smem*>(smraw);

    const int tid   = threadIdx.x;
    const int bbase = blockIdx.x * NB;
    const int w     = tid >> 5;           // 0..15
    const int wn    = w & 7;              // n-position
    const int wm    = w >> 3;             // m-group (0: mt 0-2, 1: mt 3-4)
    const int mtbase = wm * 3;
    const int mtn    = wm ? 2 : 3;
    const int lane  = tid & 31;
    const int lr    = lane >> 2;
    const int lc    = lane & 3;
    // ldmatrix per-lane offset + m-group offset
    const uint lmoff = (uint)((((lane & 15) * STB) + 8 * (lane >> 4)) * 2)
                     + (uint)(mtbase * 16 * STB * 2);
    const uint ZhU  = s2u(sm.Zh)  + lmoff, ZlU  = s2u(sm.Zl)  + lmoff;
    const uint DahU = s2u(sm.Dah) + lmoff, DalU = s2u(sm.Dal) + lmoff;
    const uint DbhU = s2u(sm.Dbh) + lmoff, DblU = s2u(sm.Dbl) + lmoff;
    // spmm map: 8 rowg x 64 col-pairs
    const int rowg_s  = tid & 7;
    const int c0_s    = 2 * (tid >> 3);
    const int rbase_s = 9 * rowg_s;
    const int bloc_s  = rowg_s >> 1;
    const int nlo_s   = (rowg_s & 1) ? 12 : 0;

    for (int i = tid; i < 2 * NNODE * NNODE; i += THREADS) {
        int s = i / (NNODE * NNODE);
        int rem = i - s * NNODE * NNODE;
        int n = rem / NNODE;
        int m = rem - n * NNODE;
        float v = sup[i];
        int ln = (n < 9) ? n : (12 + n - 9);
        sm.St2[s][m * STS2 + ln] = make_float2(v, v);
    }
    for (int i = tid; i < RB * STH; i += THREADS) {
        sm.hA[i] = 0.f; sm.hB[i] = 0.f; sm.U[i] = 0.f;
    }
    for (int i = tid; i < 6 * RBP * STB / 2; i += THREADS)
        ((uint*)sm.Zh)[i] = 0;
    __syncthreads();

    for (int t = 0; t < TSTEPS; t++) {
        for (int cell = 0; cell < 2; cell++) {
            const int CC   = cell ? 128 : 96;
            const int hoff = cell ? HIDN : DIMX;
            const int Kt   = cell ? 640 : 480;
            const float* BG = cell ? bg1 : bg0;
            const float* BC = cell ? bc1 : bc0;
            float* H = cell ? sm.hB : sm.hA;
            const ushort* WGH = cell ? g_wg1h : g_wg0h;
            const ushort* WGL = cell ? g_wg1l : g_wg0l;
            const ushort* WCH = cell ? g_wc1h : g_wc0h;
            const ushort* WCL = cell ? g_wc1l : g_wc0l;

            // ===== gate Z build =====
            if (cell == 0) {
                for (int j = tid; j < RB * 24; j += THREADS) {
                    int r = j / 24, c = 4 * (j - 24 * r);
                    float4 v;
                    if (c < DIMX) {
                        int b = bbase + r / NNODE;
                        int n = r - NNODE * (r / NNODE);
                        v = *(const float4*)(x +
                            (((size_t)b * TSTEPS + t) * NNODE + n) * DIMX + c);
                    } else {
                        v = *(const float4*)(sm.hA + r * STH + (c - DIMX));
                    }
                    uint h0, l0, h1, l1;
                    split2(v.x, v.y, h0, l0);
                    split2(v.z, v.w, h1, l1);
                    int idx = r * STB + c;
                    *(uint2*)(sm.Zh + idx) = make_uint2(h0, h1);
                    *(uint2*)(sm.Zl + idx) = make_uint2(l0, l1);
                }
            } else {
                for (int j = tid; j < RB * 32; j += THREADS) {
                    int r = j >> 5, c = 4 * (j & 31);
                    float4 v = (c < HIDN)
                        ? *(const float4*)(sm.hA + r * STH + c)
                        : *(const float4*)(sm.hB + r * STH + (c - HIDN));
                    uint h0, l0, h1, l1;
                    split2(v.x, v.y, h0, l0);
                    split2(v.z, v.w, h1, l1);
                    int idx = r * STB + c;
                    *(uint2*)(sm.Zh + idx) = make_uint2(h0, h1);
                    *(uint2*)(sm.Zl + idx) = make_uint2(l0, l1);
                }
            }
            __syncthreads();

            // ===== GATE dconv (tensor) =====
            {
                float dg[24];
#pragma unroll
                for (int q = 0; q < 24; q++) dg[q] = 0.f;
#pragma unroll 1
                for (int m = 0; m < 5; m++) {
                    uint fhU, flU;
                    if (m == 0) { fhU = ZhU; flU = ZlU; }
                    else {
                        int s = (m - 1) >> 1;
                        int second = (m - 1) & 1;
                        const ushort* srch = second ? sm.Dah : sm.Zh;
                        const ushort* srcl = second ? sm.Dal : sm.Zl;
                        ushort* dsth = second ? sm.Dbh : sm.Dah;
                        ushort* dstl = second ? sm.Dbl : sm.Dal;
                        spmm2(sm.St2[s], srch, srcl, dsth, dstl,
                              second ? sm.Zh : (const ushort*)0,
                              second ? sm.Zl : (const ushort*)0,
                              CC, rbase_s, bloc_s, nlo_s, c0_s);
                        __syncthreads();
                        fhU = second ? DbhU : DahU;
                        flU = second ? DblU : DalU;
                    }
                    if (cell) {
                        if (wm == 0) gemm_gate_mma<128, 3>(fhU, flU, WGH, WGL, Kt,
                                                           m * 128, 16 * wn, lr, lc, dg);
                        else         gemm_gate_mma<128, 2>(fhU, flU, WGH, WGL, Kt,
                                                           m * 128, 16 * wn, lr, lc, dg);
                    } else {
                        if (wm == 0) gemm_gate_mma<96, 3>(fhU, flU, WGH, WGL, Kt,
                                                          m * 96, 16 * wn, lr, lc, dg);
                        else         gemm_gate_mma<96, 2>(fhU, flU, WGH, WGL, Kt,
                                                          m * 96, 16 * wn, lr, lc, dg);
                    }
                }
#pragma unroll
                for (int j = 0; j < 2; j++) {
                    int cb = 16 * wn + 8 * j + 2 * lc;
                    float2 bv = *(const float2*)(BG + cb);
#pragma unroll
                    for (int i = 0; i < 3; i++) {
                        if (i >= mtn) break;
                        int gmt = mtbase + i;
                        float* d = dg + (j * mtn + i) * 4;
                        int r0 = gmt * 16 + lr, r1 = r0 + 8;
                        if (cb < HIDN) {
                            float2 h0 = *(const float2*)(H + r0 * STH + cb);
                            float v0 = sigm(d[0] + bv.x) * h0.x;
                            float v1 = sigm(d[1] + bv.y) * h0.y;
                            uint hh, ll;
                            split2(v0, v1, hh, ll);
                            *(uint*)(sm.Zh + r0 * STB + hoff + cb) = hh;
                            *(uint*)(sm.Zl + r0 * STB + hoff + cb) = ll;
                            if (gmt < 4) {
                                float2 h1 = *(const float2*)(H + r1 * STH + cb);
                                float v2 = sigm(d[2] + bv.x) * h1.x;
                                float v3 = sigm(d[3] + bv.y) * h1.y;
                                split2(v2, v3, hh, ll);
                                *(uint*)(sm.Zh + r1 * STB + hoff + cb) = hh;
                                *(uint*)(sm.Zl + r1 * STB + hoff + cb) = ll;
                            }
                        } else {
                            int cu = cb - HIDN;
                            *(float2*)(sm.U + r0 * STH + cu) =
                                make_float2(sigm(d[0] + bv.x), sigm(d[1] + bv.y));
                            if (gmt < 4)
                                *(float2*)(sm.U + r1 * STH + cu) =
                                    make_float2(sigm(d[2] + bv.x), sigm(d[3] + bv.y));
                        }
                    }
                }
            }
            __syncthreads();

            // ===== CANDIDATE dconv (tensor) + fused GRU update =====
            {
                float dc[12];
#pragma unroll
                for (int q = 0; q < 12; q++) dc[q] = 0.f;
#pragma unroll 1
                for (int m = 0; m < 5; m++) {
                    uint fhU, flU;
                    if (m == 0) { fhU = ZhU; flU = ZlU; }
                    else {
                        int s = (m - 1) >> 1;
                        int second = (m - 1) & 1;
                        const ushort* srch = second ? sm.Dah : sm.Zh;
                        const ushort* srcl = second ? sm.Dal : sm.Zl;
                        ushort* dsth = second ? sm.Dbh : sm.Dah;
                        ushort* dstl = second ? sm.Dbl : sm.Dal;
                        spmm2(sm.St2[s], srch, srcl, dsth, dstl,
                              second ? sm.Zh : (const ushort*)0,
                              second ? sm.Zl : (const ushort*)0,
                              CC, rbase_s, bloc_s, nlo_s, c0_s);
                        __syncthreads();
                        fhU = second ? DbhU : DahU;
                        flU = second ? DblU : DalU;
                    }
                    if (cell) {
                        if (wm == 0) gemm_cand_mma<128, 3>(fhU, flU, WCH, WCL, Kt,
                                                           m * 128, 8 * wn, lr, lc, dc);
                        else         gemm_cand_mma<128, 2>(fhU, flU, WCH, WCL, Kt,
                                                           m * 128, 8 * wn, lr, lc, dc);
                    } else {
                        if (wm == 0) gemm_cand_mma<96, 3>(fhU, flU, WCH, WCL, Kt,
                                                          m * 96, 8 * wn, lr, lc, dc);
                        else         gemm_cand_mma<96, 2>(fhU, flU, WCH, WCL, Kt,
                                                          m * 96, 8 * wn, lr, lc, dc);
                    }
                }
                {
                    int cb = 8 * wn + 2 * lc;
                    float2 bv = *(const float2*)(BC + cb);
#pragma unroll
                    for (int i = 0; i < 3; i++) {
                        if (i >= mtn) break;
                        int gmt = mtbase + i;
                        float* d = dc + i * 4;
                        int r0 = gmt * 16 + lr, r1 = r0 + 8;
                        {
                            float c0v = tanh_(d[0] + bv.x), c1v = tanh_(d[1] + bv.y);
                            float2 u0 = *(const float2*)(sm.U + r0 * STH + cb);
                            float2 h0 = *(const float2*)(H + r0 * STH + cb);
                            *(float2*)(H + r0 * STH + cb) =
                                make_float2(c0v + u0.x * (h0.x - c0v),
                                            c1v + u0.y * (h0.y - c1v));
                        }
                        if (gmt < 4) {
                            float c2v = tanh_(d[2] + bv.x), c3v = tanh_(d[3] + bv.y);
                            float2 u1 = *(const float2*)(sm.U + r1 * STH + cb);
                            float2 h1 = *(const float2*)(H + r1 * STH + cb);
                            *(float2*)(H + r1 * STH + cb) =
                                make_float2(c2v + u1.x * (h1.x - c2v),
                                            c3v + u1.y * (h1.y - c3v));
                        }
                    }
                }
            }
            __syncthreads();
        } // cell
    } // t

    // ---- epilogue ----
    if (tid < RB) {
        float acc = fcb[0];
#pragma unroll
        for (int c = 0; c < HIDN; c++)
            acc += fmaxf(sm.hB[tid * STH + c], 0.f) * fcw[c];
        sm.U[tid] = acc;
    }
    __syncthreads();
    if (tid < NB) {
        float mx = -3.4e38f;
#pragma unroll
        for (int n = 0; n < NNODE; n++)
            mx = fmaxf(mx, sm.U[tid * NNODE + n]);
        out[bbase + tid] = mx;
    }
}

extern "C" void kernel_launch(void* const* d_in, const int* in_sizes, int n_in,
                              void* d_out, int out_size)
{
    (void)in_sizes; (void)n_in; (void)out_size;
    const size_t shbytes = sizeof(Smem);
    cudaFuncSetAttribute(dcrnn_kernel,
                         cudaFuncAttributeMaxDynamicSharedMemorySize,
                         (int)shbytes);
    pack_kernel<<<(215040 + 255) / 256, 256>>>(
        (const float*)d_in[2], (const float*)d_in[4],
        (const float*)d_in[6], (const float*)d_in[8]);
    dcrnn_kernel<<<NBLK, THREADS, shbytes>>>(
        (const float*)d_in[0],  (const float*)d_in[1],
        (const float*)d_in[3],  (const float*)d_in[5],
        (const float*)d_in[7],  (const float*)d_in[9],
        (const float*)d_in[10], (const float*)d_in[11],
        (float*)d_out);
}